// round 14
// baseline (speedup 1.0000x reference)
#include <cuda_runtime.h>
#include <cuda_fp16.h>
#include <math.h>

// DisneyNet: pointwise shading eval with table gathers.
// Depth-2 gather pipeline held in SMEM via cp.async (not registers), so the
// pipeline cannot be sunk by ptxas and costs no live registers. This frees
// the register budget for 704 thr x 2 CTA/SM = 44 warps. rn/at are re-read
// in the body (L1 hits; prefetch uses default caching).

static __device__ __forceinline__ float triw(float x) {
    return 2.0f * fabsf(0.5f * x - floorf(0.5f * x + 0.5f));
}

static __device__ __forceinline__ float clip01(float x) {
    return fminf(fmaxf(x, 0.0f), 1.0f - 1e-6f);
}

// ---- shared memory layout (in floats) ----
static constexpr int NTHR = 704;
static constexpr int OFF_RS   = 0;                  // 64x64 half4 (triw) -> 8192
static constexpr int OFF_LV   = OFF_RS   + 8192;    // 32x32 half4 (triw) -> 2048
static constexpr int OFF_NHL  = OFF_LV   + 2048;    // 32x32 half4 (triw) -> 2048
static constexpr int OFF_RA01 = OFF_NHL  + 2048;    // 48x48 float2       -> 4608
static constexpr int OFF_RA2  = OFF_RA01 + 4608;    // 48x48 float        -> 2304
static constexpr int OFF_LVR  = OFF_RA2  + 2304;    // 32x32 half (triw)  ->  512
static constexpr int OFF_CGF  = OFF_LVR  + 512;     // 2048 float2 fused  -> 4096
static constexpr int OFF_GB   = OFF_CGF  + 4096;    // gather ring: 3 x NTHR float2
static constexpr int SMEM_FLOATS = OFF_GB + 3 * NTHR * 2;
static constexpr int SMEM_BYTES  = SMEM_FLOATS * 4;   // 112128 B

struct Bl { int i00, i10, i01, i11; float w00, w10, w01, w11; };
// No-clip bilinear setup: caller guarantees cu, cv in [0, 1).
template <int U, int V>
static __device__ __forceinline__ Bl bl_setup(float cu, float cv) {
    float u = cu * (float)(U - 1);
    float v = cv * (float)(V - 1);
    float u0f = floorf(u), v0f = floorf(v);
    float fu = u - u0f, fv = v - v0f;
    int u0 = (int)u0f, v0 = (int)v0f;
    int base = u0 * V + v0;
    Bl b;
    b.i00 = base;     b.i10 = base + V;
    b.i01 = base + 1; b.i11 = base + V + 1;
    b.w00 = (1.0f - fu) * (1.0f - fv);
    b.w10 = fu * (1.0f - fv);
    b.w01 = (1.0f - fu) * fv;
    b.w11 = fu * fv;
    return b;
}

static __device__ __forceinline__ float4 ld_h4(const uint2* __restrict__ s, int idx) {
    uint2 r = s[idx];
    __half2 h01 = *reinterpret_cast<__half2*>(&r.x);
    __half2 h23 = *reinterpret_cast<__half2*>(&r.y);
    float2 f01 = __half22float2(h01);
    float2 f23 = __half22float2(h23);
    return make_float4(f01.x, f01.y, f23.x, f23.y);
}

template <int U, int V>
static __device__ __forceinline__ float4 bilin_h4(const uint2* __restrict__ s,
                                                  float cu, float cv) {
    Bl b = bl_setup<U, V>(cu, cv);
    float4 a = ld_h4(s, b.i00);
    float4 c = ld_h4(s, b.i10);
    float4 d = ld_h4(s, b.i01);
    float4 e = ld_h4(s, b.i11);
    float4 o;
    o.x = a.x * b.w00 + c.x * b.w10 + d.x * b.w01 + e.x * b.w11;
    o.y = a.y * b.w00 + c.y * b.w10 + d.y * b.w01 + e.y * b.w11;
    o.z = a.z * b.w00 + c.z * b.w10 + d.z * b.w01 + e.z * b.w11;
    o.w = a.w * b.w00 + c.w * b.w10 + d.w * b.w01 + e.w * b.w11;
    return o;
}

static __device__ __forceinline__ void cp_async8(unsigned saddr, const void* g) {
    asm volatile("cp.async.ca.shared.global [%0], [%1], 8;"
                 :: "r"(saddr), "l"(g) : "memory");
}
static __device__ __forceinline__ void cp_commit() {
    asm volatile("cp.async.commit_group;" ::: "memory");
}
static __device__ __forceinline__ void cp_wait2() {
    asm volatile("cp.async.wait_group 2;" ::: "memory");
}

static __device__ __forceinline__ float2 ldcs2(const float2* p) {
    return __ldcs(p);
}

__global__ void __launch_bounds__(NTHR, 2)
disneynet_kernel(const float2* __restrict__ roughNoh,
                 const float2* __restrict__ anisoToh,
                 const float2* __restrict__ nDotLV,
                 const float2* __restrict__ metalLoh,
                 const float2* __restrict__ subCg,
                 const float2* __restrict__ spst,
                 const float2* __restrict__ shst,
                 const float2* __restrict__ lumCs,
                 const float2* __restrict__ tabRAEnc,  // 2048x2048x2 (global/L2)
                 const float*  __restrict__ tabCgEnc,  // 2048
                 const float*  __restrict__ tabRSEnc,  // 64x64x3
                 const float*  __restrict__ tabRADec,  // 48x48x3
                 const float2* __restrict__ tabCgDec,  // 96x2
                 const float*  __restrict__ tabLVR,    // 32x32
                 const float4* __restrict__ tabLV,     // 32x32x4
                 const float4* __restrict__ tabNHL,    // 32x32x4
                 float2* __restrict__ out,
                 int n) {
    extern __shared__ float smem[];
    uint2*  sRS   = (uint2*)(smem + OFF_RS);
    uint2*  sLV   = (uint2*)(smem + OFF_LV);
    uint2*  sNHL  = (uint2*)(smem + OFF_NHL);
    float2* sRA01 = (float2*)(smem + OFF_RA01);
    float*  sRA2  = smem + OFF_RA2;
    __half* sLVR  = (__half*)(smem + OFF_LVR);
    float2* sCgF  = (float2*)(smem + OFF_CGF);
    float2* sGB   = (float2*)(smem + OFF_GB);   // [3][NTHR]

    const int tid = threadIdx.x;
    const int nthr = blockDim.x;

    // ---- stage tables ----
    for (int idx = tid; idx < 64 * 64; idx += nthr) {
        const float* src = tabRSEnc + idx * 3;
        __half2 h01 = __floats2half2_rn(triw(src[0]), triw(src[1]));
        __half2 h23 = __floats2half2_rn(triw(src[2]), 0.0f);
        uint2 r;
        r.x = *reinterpret_cast<unsigned*>(&h01);
        r.y = *reinterpret_cast<unsigned*>(&h23);
        sRS[idx] = r;
    }
    for (int idx = tid; idx < 32 * 32; idx += nthr) {
        float4 v = tabLV[idx];
        __half2 a = __floats2half2_rn(triw(v.x), triw(v.y));
        __half2 b = __floats2half2_rn(triw(v.z), triw(v.w));
        uint2 r;
        r.x = *reinterpret_cast<unsigned*>(&a);
        r.y = *reinterpret_cast<unsigned*>(&b);
        sLV[idx] = r;
        float4 w = tabNHL[idx];
        __half2 c = __floats2half2_rn(triw(w.x), triw(w.y));
        __half2 d = __floats2half2_rn(triw(w.z), triw(w.w));
        uint2 q;
        q.x = *reinterpret_cast<unsigned*>(&c);
        q.y = *reinterpret_cast<unsigned*>(&d);
        sNHL[idx] = q;
        sLVR[idx] = __float2half_rn(triw(tabLVR[idx]));
    }
    for (int idx = tid; idx < 48 * 48; idx += nthr) {
        const float* src = tabRADec + idx * 3;
        sRA01[idx] = make_float2(src[0], src[1]);
        sRA2[idx]  = src[2];
    }
    // Fused cg chain: ci -> triw(tabCgEnc[ci]) -> bilinear(tabCgDec).
    for (int idx = tid; idx < 2048; idx += nthr) {
        float cg0 = triw(tabCgEnc[idx]);
        float u = clip01(cg0) * 95.0f;
        float u0f = floorf(u);
        float fu = u - u0f;
        int u0 = (int)u0f;
        int u1 = min(u0 + 1, 95);
        float2 a = tabCgDec[u0];
        float2 b = tabCgDec[u1];
        sCgF[idx] = make_float2(a.x * (1.0f - fu) + b.x * fu,
                                a.y * (1.0f - fu) + b.y * fu);
    }
    __syncthreads();

    const unsigned sGBaddr =
        (unsigned)__cvta_generic_to_shared(smem + OFF_GB);

    const int stride = gridDim.x * nthr;
    const int i0 = blockIdx.x * nthr + tid;

    // Prologue: fill slots 0 (point i0) and 1 (point i0+stride).
    if (i0 < n) {
        float2 rnp = __ldg(roughNoh + i0);
        float2 atp = __ldg(anisoToh + i0);
        int ui = (int)rintf(rnp.x * 2047.0f);
        int vi = (int)rintf(atp.x * 2047.0f);
        cp_async8(sGBaddr + (unsigned)(0 * nthr + tid) * 8u,
                  tabRAEnc + (ui * 2048 + vi));
    }
    cp_commit();
    if (i0 + stride < n) {
        float2 rnp = __ldg(roughNoh + i0 + stride);
        float2 atp = __ldg(anisoToh + i0 + stride);
        int ui = (int)rintf(rnp.x * 2047.0f);
        int vi = (int)rintf(atp.x * 2047.0f);
        cp_async8(sGBaddr + (unsigned)(1 * nthr + tid) * 8u,
                  tabRAEnc + (ui * 2048 + vi));
    }
    cp_commit();

    int consume = 0;   // ring slot holding point i's gather
    for (int i = i0; i < n; i += stride) {
        // Prefetch gather for i + 2*stride into slot (consume+2)%3.
        const int k = i + 2 * stride;
        int wslot = consume + 2; if (wslot >= 3) wslot -= 3;
        if (k < n) {
            float2 rnp = __ldg(roughNoh + k);
            float2 atp = __ldg(anisoToh + k);
            int ui = (int)rintf(rnp.x * 2047.0f);
            int vi = (int)rintf(atp.x * 2047.0f);
            cp_async8(sGBaddr + (unsigned)(wslot * nthr + tid) * 8u,
                      tabRAEnc + (ui * 2048 + vi));
        }
        cp_commit();
        cp_wait2();   // slot `consume` (committed 2 iters ago) is complete

        float2 gA = sGB[consume * nthr + tid];

        // rn/at re-read: prefetch touched these lines with default caching,
        // so these are L1 hits.
        const float2 rn = __ldg(roughNoh + i);
        const float2 at = __ldg(anisoToh + i);
        const float2 nl = ldcs2(nDotLV + i);
        const float2 ml = ldcs2(metalLoh + i);
        const float2 sc = ldcs2(subCg + i);
        const float2 sp = ldcs2(spst + i);
        const float2 sh = ldcs2(shst + i);
        const float2 lc = ldcs2(lumCs + i);

        // triw is identity on [0,1): gathered values used directly as coords.
        const float ra0 = gA.x;
        const float ra1 = gA.y;

        // fused cg -> (cgC0, cgC1)
        int ci = (int)rintf(sc.y * 2047.0f);
        float2 cgC = sCgF[ci];

        // rsEnc = bilinear (pre-normalized fp16 values, fp32 accumulate)
        float4 rs = bilin_h4<64, 64>(sRS, rn.x, sc.x);

        const float m = ml.x;
        const float om = 1.0f - m;
        const float cd  = om * lc.x;
        const float cm0 = sp.x * 0.1f * om * sp.y + m * lc.x;
        const float cm1 = sp.x * 0.1f * om * (1.0f - sp.y);
        const float cs0 = sh.x * om * sh.y;
        const float cs1 = sh.x * om * (1.0f - sh.y);
        const float ccv = 0.0625f * lc.y;

        const float rsCd0 = rs.x * cd;
        const float rsCd1 = rs.y * cd;
        const float rsCd2 = rs.z * cd;

        // raCoefs = bilinear, fp32 SoA (feeds den^2)
        float raC0, raC1, raC2;
        {
            Bl b = bl_setup<48, 48>(ra0, ra1);
            float2 a = sRA01[b.i00];
            float2 c = sRA01[b.i10];
            float2 d = sRA01[b.i01];
            float2 e = sRA01[b.i11];
            raC0 = a.x * b.w00 + c.x * b.w10 + d.x * b.w01 + e.x * b.w11;
            raC1 = a.y * b.w00 + c.y * b.w10 + d.y * b.w01 + e.y * b.w11;
            raC2 = sRA2[b.i00] * b.w00 + sRA2[b.i10] * b.w10
                 + sRA2[b.i01] * b.w01 + sRA2[b.i11] * b.w11;
        }

        // vTerm = bilinear, fp16 scalar table, fp32 accumulate
        float vT;
        {
            Bl b = bl_setup<32, 32>(nl.x * nl.y, ra0);
            float a = __half2float(sLVR[b.i00]);
            float c = __half2float(sLVR[b.i10]);
            float d = __half2float(sLVR[b.i01]);
            float e = __half2float(sLVR[b.i11]);
            vT = a * b.w00 + c * b.w10 + d * b.w01 + e * b.w11;
        }

        // nlvCoefs / nhlCoefs: fp16 values, fp32 interpolation
        float4 nlv = bilin_h4<32, 32>(sLV, nl.x, nl.y);
        float4 nhl = bilin_h4<32, 32>(sNHL, ml.y, nl.x);

        const float noh2 = rn.y * rn.y;
        const float den = raC0 * at.y * at.y + raC1 * noh2 + raC2;
        const float dT = __fdividef(0.25f, nl.y * den * den);

        float x = rsCd0 * ml.y * nlv.y
                + rsCd1 * nlv.z
                + rsCd2 * nlv.w
                + cm0 * vT * nhl.z * dT
                + cs0 * nhl.x;

        float y = ((1.0f - cm1) * nhl.w + cm1) * vT * dT
                + cs1 * nhl.x
                + ccv * nhl.y * nlv.x * __fdividef(1.0f, nl.y * (cgC.x * noh2 + cgC.y));

        __stcs(out + i, make_float2(x, y));

        consume = consume + 1; if (consume >= 3) consume = 0;
    }
}

extern "C" void kernel_launch(void* const* d_in, const int* in_sizes, int n_in,
                              void* d_out, int out_size) {
    // Input order:
    // 0 roughNoh 1 anisoToh 2 nDotLV 3 tDotLV(unused) 4 metalLoh 5 subCg
    // 6 spst 7 shst 8 lumCs 9 tabRAEnc 10 tabCgEnc 11 tabRSEnc 12 tabRADec
    // 13 tabCgDec 14 tabLVR 15 tabLV 16 tabNHL
    const int n = in_sizes[0] / 2;

    static bool attr_set = false;
    if (!attr_set) {
        cudaFuncSetAttribute(disneynet_kernel,
                             cudaFuncAttributeMaxDynamicSharedMemorySize,
                             SMEM_BYTES);
        attr_set = true;
    }

    const int threads = NTHR;
    const int blocks = 296;  // 2 CTAs/SM x 148 SMs, persistent
    disneynet_kernel<<<blocks, threads, SMEM_BYTES>>>(
        (const float2*)d_in[0],
        (const float2*)d_in[1],
        (const float2*)d_in[2],
        (const float2*)d_in[4],
        (const float2*)d_in[5],
        (const float2*)d_in[6],
        (const float2*)d_in[7],
        (const float2*)d_in[8],
        (const float2*)d_in[9],
        (const float*)d_in[10],
        (const float*)d_in[11],
        (const float*)d_in[12],
        (const float2*)d_in[13],
        (const float*)d_in[14],
        (const float4*)d_in[15],
        (const float4*)d_in[16],
        (float2*)d_out,
        n);
}

// round 15
// speedup vs baseline: 1.1567x; 1.1567x over previous
#include <cuda_runtime.h>
#include <cuda_fp16.h>
#include <math.h>

// DisneyNet: pointwise shading eval with table gathers.
// Best-known structure: 640 thr x 2 CTA/SM persistent, depth-1 register
// pipeline on the tabRAEnc gather (48-reg live set; caps below that destroy
// it), fp16 smem LUT values with fp32 interpolation, fused cg chain, lean
// body (no clip/triw on provably-[0,1) data). New: vertical pair-packing of
// the LVR and RA2 tables halves their LDS count (4->2 loads each).

static __device__ __forceinline__ float triw(float x) {
    return 2.0f * fabsf(0.5f * x - floorf(0.5f * x + 0.5f));
}

static __device__ __forceinline__ float clip01(float x) {
    return fminf(fmaxf(x, 0.0f), 1.0f - 1e-6f);
}

// ---- shared memory layout (in floats) ----
static constexpr int OFF_RS   = 0;                  // 64x64 half4 (triw)    -> 8192
static constexpr int OFF_LV   = OFF_RS   + 8192;    // 32x32 half4 (triw)    -> 2048
static constexpr int OFF_NHL  = OFF_LV   + 2048;    // 32x32 half4 (triw)    -> 2048
static constexpr int OFF_RA01 = OFF_NHL  + 2048;    // 48x48 float2          -> 4608
static constexpr int OFF_RA2P = OFF_RA01 + 4608;    // 48x48 float2 vpair    -> 4608
static constexpr int OFF_LVRP = OFF_RA2P + 4608;    // 32x32 half2 vpair     -> 1024
static constexpr int OFF_CGF  = OFF_LVRP + 1024;    // 2048 float2 fused     -> 4096
static constexpr int SMEM_FLOATS = OFF_CGF + 4096;
static constexpr int SMEM_BYTES  = SMEM_FLOATS * 4;   // 106496 B

struct Bl { int i00, i10, i01, i11; float w00, w10, w01, w11; };
// No-clip bilinear setup: caller guarantees cu, cv in [0, 1).
template <int U, int V>
static __device__ __forceinline__ Bl bl_setup(float cu, float cv) {
    float u = cu * (float)(U - 1);
    float v = cv * (float)(V - 1);
    float u0f = floorf(u), v0f = floorf(v);
    float fu = u - u0f, fv = v - v0f;
    int u0 = (int)u0f, v0 = (int)v0f;
    int base = u0 * V + v0;
    Bl b;
    b.i00 = base;     b.i10 = base + V;
    b.i01 = base + 1; b.i11 = base + V + 1;
    b.w00 = (1.0f - fu) * (1.0f - fv);
    b.w10 = fu * (1.0f - fv);
    b.w01 = (1.0f - fu) * fv;
    b.w11 = fu * fv;
    return b;
}

static __device__ __forceinline__ float4 ld_h4(const uint2* __restrict__ s, int idx) {
    uint2 r = s[idx];
    __half2 h01 = *reinterpret_cast<__half2*>(&r.x);
    __half2 h23 = *reinterpret_cast<__half2*>(&r.y);
    float2 f01 = __half22float2(h01);
    float2 f23 = __half22float2(h23);
    return make_float4(f01.x, f01.y, f23.x, f23.y);
}

template <int U, int V>
static __device__ __forceinline__ float4 bilin_h4(const uint2* __restrict__ s,
                                                  float cu, float cv) {
    Bl b = bl_setup<U, V>(cu, cv);
    float4 a = ld_h4(s, b.i00);
    float4 c = ld_h4(s, b.i10);
    float4 d = ld_h4(s, b.i01);
    float4 e = ld_h4(s, b.i11);
    float4 o;
    o.x = a.x * b.w00 + c.x * b.w10 + d.x * b.w01 + e.x * b.w11;
    o.y = a.y * b.w00 + c.y * b.w10 + d.y * b.w01 + e.y * b.w11;
    o.z = a.z * b.w00 + c.z * b.w10 + d.z * b.w01 + e.z * b.w11;
    o.w = a.w * b.w00 + c.w * b.w10 + d.w * b.w01 + e.w * b.w11;
    return o;
}

static __device__ __forceinline__ float2 gather_ra(const float2* __restrict__ t,
                                                   float rx, float ax) {
    int ui = (int)rintf(rx * 2047.0f);
    int vi = (int)rintf(ax * 2047.0f);
    return __ldg(t + (ui * 2048 + vi));
}

static __device__ __forceinline__ float2 ldcs2(const float2* p) {
    return __ldcs(p);
}

__global__ void __launch_bounds__(640, 2)
disneynet_kernel(const float2* __restrict__ roughNoh,
                 const float2* __restrict__ anisoToh,
                 const float2* __restrict__ nDotLV,
                 const float2* __restrict__ metalLoh,
                 const float2* __restrict__ subCg,
                 const float2* __restrict__ spst,
                 const float2* __restrict__ shst,
                 const float2* __restrict__ lumCs,
                 const float2* __restrict__ tabRAEnc,  // 2048x2048x2 (global/L2)
                 const float*  __restrict__ tabCgEnc,  // 2048
                 const float*  __restrict__ tabRSEnc,  // 64x64x3
                 const float*  __restrict__ tabRADec,  // 48x48x3
                 const float2* __restrict__ tabCgDec,  // 96x2
                 const float*  __restrict__ tabLVR,    // 32x32
                 const float4* __restrict__ tabLV,     // 32x32x4
                 const float4* __restrict__ tabNHL,    // 32x32x4
                 float2* __restrict__ out,
                 int n) {
    extern __shared__ float smem[];
    uint2*   sRS   = (uint2*)(smem + OFF_RS);
    uint2*   sLV   = (uint2*)(smem + OFF_LV);
    uint2*   sNHL  = (uint2*)(smem + OFF_NHL);
    float2*  sRA01 = (float2*)(smem + OFF_RA01);
    float2*  sRA2P = (float2*)(smem + OFF_RA2P);   // vertical pairs
    __half2* sLVRP = (__half2*)(smem + OFF_LVRP);  // vertical pairs
    float2*  sCgF  = (float2*)(smem + OFF_CGF);

    const int tid = threadIdx.x;
    const int nthr = blockDim.x;

    // ---- stage tables ----
    for (int idx = tid; idx < 64 * 64; idx += nthr) {
        const float* src = tabRSEnc + idx * 3;
        __half2 h01 = __floats2half2_rn(triw(src[0]), triw(src[1]));
        __half2 h23 = __floats2half2_rn(triw(src[2]), 0.0f);
        uint2 r;
        r.x = *reinterpret_cast<unsigned*>(&h01);
        r.y = *reinterpret_cast<unsigned*>(&h23);
        sRS[idx] = r;
    }
    for (int idx = tid; idx < 32 * 32; idx += nthr) {
        int u = idx / 32, v = idx % 32;
        float4 vv = tabLV[idx];
        __half2 a = __floats2half2_rn(triw(vv.x), triw(vv.y));
        __half2 b = __floats2half2_rn(triw(vv.z), triw(vv.w));
        uint2 r;
        r.x = *reinterpret_cast<unsigned*>(&a);
        r.y = *reinterpret_cast<unsigned*>(&b);
        sLV[idx] = r;
        float4 w = tabNHL[idx];
        __half2 c = __floats2half2_rn(triw(w.x), triw(w.y));
        __half2 d = __floats2half2_rn(triw(w.z), triw(w.w));
        uint2 q;
        q.x = *reinterpret_cast<unsigned*>(&c);
        q.y = *reinterpret_cast<unsigned*>(&d);
        sNHL[idx] = q;
        // vertical pair: (t[u][v], t[u+1][v]); u=31 row never read as a pair base
        int u1 = min(u + 1, 31);
        sLVRP[idx] = __floats2half2_rn(triw(tabLVR[u * 32 + v]),
                                       triw(tabLVR[u1 * 32 + v]));
    }
    for (int idx = tid; idx < 48 * 48; idx += nthr) {
        int u = idx / 48, v = idx % 48;
        const float* src = tabRADec + idx * 3;
        sRA01[idx] = make_float2(src[0], src[1]);
        int u1 = min(u + 1, 47);
        sRA2P[idx] = make_float2(tabRADec[(u * 48 + v) * 3 + 2],
                                 tabRADec[(u1 * 48 + v) * 3 + 2]);
    }
    // Fused cg chain: ci -> triw(tabCgEnc[ci]) -> bilinear(tabCgDec).
    for (int idx = tid; idx < 2048; idx += nthr) {
        float cg0 = triw(tabCgEnc[idx]);
        float u = clip01(cg0) * 95.0f;
        float u0f = floorf(u);
        float fu = u - u0f;
        int u0 = (int)u0f;
        int u1 = min(u0 + 1, 95);
        float2 a = tabCgDec[u0];
        float2 b = tabCgDec[u1];
        sCgF[idx] = make_float2(a.x * (1.0f - fu) + b.x * fu,
                                a.y * (1.0f - fu) + b.y * fu);
    }
    __syncthreads();

    const int stride = gridDim.x * nthr;
    const int i0 = blockIdx.x * nthr + tid;

    // Prologue: first iteration's gather (depth-1 register pipeline).
    float2 rn, at, raRaw;
    if (i0 < n) {
        rn = ldcs2(roughNoh + i0);
        at = ldcs2(anisoToh + i0);
        raRaw = gather_ra(tabRAEnc, rn.x, at.x);
    }

    for (int i = i0; i < n; i += stride) {
        // Prefetch next iteration's gather.
        const int j = i + stride;
        float2 rn_n, at_n, raRaw_n;
        if (j < n) {
            rn_n = ldcs2(roughNoh + j);
            at_n = ldcs2(anisoToh + j);
            raRaw_n = gather_ra(tabRAEnc, rn_n.x, at_n.x);
        }

        const float2 nl = ldcs2(nDotLV + i);
        const float2 ml = ldcs2(metalLoh + i);
        const float2 sc = ldcs2(subCg + i);
        const float2 sp = ldcs2(spst + i);
        const float2 sh = ldcs2(shst + i);
        const float2 lc = ldcs2(lumCs + i);

        // triw identity on [0,1): gathered values used directly.
        const float ra0 = raRaw.x;
        const float ra1 = raRaw.y;

        // fused cg -> (cgC0, cgC1)
        int ci = (int)rintf(sc.y * 2047.0f);
        float2 cgC = sCgF[ci];

        // rsEnc = bilinear (pre-normalized fp16 values, fp32 accumulate)
        float4 rs = bilin_h4<64, 64>(sRS, rn.x, sc.x);

        const float m = ml.x;
        const float om = 1.0f - m;
        const float cd  = om * lc.x;
        const float cm0 = sp.x * 0.1f * om * sp.y + m * lc.x;
        const float cm1 = sp.x * 0.1f * om * (1.0f - sp.y);
        const float cs0 = sh.x * om * sh.y;
        const float cs1 = sh.x * om * (1.0f - sh.y);
        const float ccv = 0.0625f * lc.y;

        const float rsCd0 = rs.x * cd;
        const float rsCd1 = rs.y * cd;
        const float rsCd2 = rs.z * cd;

        // raCoefs: ch0/ch1 from float2 corners, ch2 from vertical pairs.
        float raC0, raC1, raC2;
        {
            Bl b = bl_setup<48, 48>(ra0, ra1);
            float2 a = sRA01[b.i00];
            float2 c = sRA01[b.i10];
            float2 d = sRA01[b.i01];
            float2 e = sRA01[b.i11];
            raC0 = a.x * b.w00 + c.x * b.w10 + d.x * b.w01 + e.x * b.w11;
            raC1 = a.y * b.w00 + c.y * b.w10 + d.y * b.w01 + e.y * b.w11;
            // pair q.x = t2[u0][v], q.y = t2[u0+1][v]
            float2 q0 = sRA2P[b.i00];   // v = v0
            float2 q1 = sRA2P[b.i01];   // v = v0+1
            raC2 = q0.x * b.w00 + q0.y * b.w10 + q1.x * b.w01 + q1.y * b.w11;
        }

        // vTerm: vertical-pair half2 table, 2 loads.
        float vT;
        {
            Bl b = bl_setup<32, 32>(nl.x * nl.y, ra0);
            float2 p0 = __half22float2(sLVRP[b.i00]);  // (t[u0][v0], t[u1][v0])
            float2 p1 = __half22float2(sLVRP[b.i01]);  // (t[u0][v1], t[u1][v1])
            vT = p0.x * b.w00 + p0.y * b.w10 + p1.x * b.w01 + p1.y * b.w11;
        }

        // nlvCoefs / nhlCoefs: fp16 values, fp32 interpolation
        float4 nlv = bilin_h4<32, 32>(sLV, nl.x, nl.y);
        float4 nhl = bilin_h4<32, 32>(sNHL, ml.y, nl.x);

        const float noh2 = rn.y * rn.y;
        const float den = raC0 * at.y * at.y + raC1 * noh2 + raC2;
        const float dT = __fdividef(0.25f, nl.y * den * den);

        float x = rsCd0 * ml.y * nlv.y
                + rsCd1 * nlv.z
                + rsCd2 * nlv.w
                + cm0 * vT * nhl.z * dT
                + cs0 * nhl.x;

        float y = ((1.0f - cm1) * nhl.w + cm1) * vT * dT
                + cs1 * nhl.x
                + ccv * nhl.y * nlv.x * __fdividef(1.0f, nl.y * (cgC.x * noh2 + cgC.y));

        __stcs(out + i, make_float2(x, y));

        // rotate pipeline
        rn = rn_n;
        at = at_n;
        raRaw = raRaw_n;
    }
}

extern "C" void kernel_launch(void* const* d_in, const int* in_sizes, int n_in,
                              void* d_out, int out_size) {
    // Input order:
    // 0 roughNoh 1 anisoToh 2 nDotLV 3 tDotLV(unused) 4 metalLoh 5 subCg
    // 6 spst 7 shst 8 lumCs 9 tabRAEnc 10 tabCgEnc 11 tabRSEnc 12 tabRADec
    // 13 tabCgDec 14 tabLVR 15 tabLV 16 tabNHL
    const int n = in_sizes[0] / 2;

    static bool attr_set = false;
    if (!attr_set) {
        cudaFuncSetAttribute(disneynet_kernel,
                             cudaFuncAttributeMaxDynamicSharedMemorySize,
                             SMEM_BYTES);
        attr_set = true;
    }

    const int threads = 640;
    const int blocks = 296;  // 2 CTAs/SM x 148 SMs, persistent
    disneynet_kernel<<<blocks, threads, SMEM_BYTES>>>(
        (const float2*)d_in[0],
        (const float2*)d_in[1],
        (const float2*)d_in[2],
        (const float2*)d_in[4],
        (const float2*)d_in[5],
        (const float2*)d_in[6],
        (const float2*)d_in[7],
        (const float2*)d_in[8],
        (const float2*)d_in[9],
        (const float*)d_in[10],
        (const float*)d_in[11],
        (const float*)d_in[12],
        (const float2*)d_in[13],
        (const float*)d_in[14],
        (const float4*)d_in[15],
        (const float4*)d_in[16],
        (float2*)d_out,
        n);
}

// round 16
// speedup vs baseline: 1.5412x; 1.3325x over previous
#include <cuda_runtime.h>
#include <cuda_fp16.h>
#include <math.h>

// DisneyNet: pointwise shading eval with table gathers.
// CONVERGED BEST (R7 config, 49.6us): persistent kernel, 1 point/thread,
// depth-1 register-pipelined tabRAEnc gather, fp16 smem LUT values with fp32
// interpolation, fused cg chain, float2+float RA corners, streaming cache
// hints on one-pass data. 640 thr x 2 CTA/SM = 40 warps/SM.
//
// Session findings (all measured):
//  - L1tex wavefront throughput + gather latency exposure is the wall;
//    four distinct configs all pin at 49.63us.
//  - Pipeline needs ~48 live regs; reg caps below that make ptxas sink the
//    prefetch (R8: 64us). ILP-2/point halves warps and regresses (R6: 57us).
//  - LDS.128 random corners worse than LDS.64+.32 (R9: 60us). smem cp.async
//    ring serializes on its own address load (R14: 77us). vpair packing
//    perturbs the schedule and regresses (R15: 66us).
//  - evict_last hint: no-op (R11). Depth-2 at 36 warps == depth-1 at 40 (R12).

static __device__ __forceinline__ float triw(float x) {
    return 2.0f * fabsf(0.5f * x - floorf(0.5f * x + 0.5f));
}

static __device__ __forceinline__ float clip01(float x) {
    return fminf(fmaxf(x, 0.0f), 1.0f - 1e-6f);
}

// ---- shared memory layout (in floats) ----
static constexpr int OFF_RS   = 0;                  // 64x64 half4 (triw) -> 8192
static constexpr int OFF_LV   = OFF_RS   + 8192;    // 32x32 half4 (triw) -> 2048
static constexpr int OFF_NHL  = OFF_LV   + 2048;    // 32x32 half4 (triw) -> 2048
static constexpr int OFF_RA01 = OFF_NHL  + 2048;    // 48x48 float2       -> 4608
static constexpr int OFF_RA2  = OFF_RA01 + 4608;    // 48x48 float        -> 2304
static constexpr int OFF_LVR  = OFF_RA2  + 2304;    // 32x32 half (triw)  ->  512
static constexpr int OFF_CGF  = OFF_LVR  + 512;     // 2048 float2 fused  -> 4096
static constexpr int SMEM_FLOATS = OFF_CGF + 4096;
static constexpr int SMEM_BYTES  = SMEM_FLOATS * 4;   // 95232 B

struct Bl { int i00, i10, i01, i11; float w00, w10, w01, w11; };
template <int U, int V>
static __device__ __forceinline__ Bl bl_setup(float cu, float cv) {
    float u = clip01(cu) * (float)(U - 1);
    float v = clip01(cv) * (float)(V - 1);
    float u0f = floorf(u), v0f = floorf(v);
    float fu = u - u0f, fv = v - v0f;
    int u0 = (int)u0f, v0 = (int)v0f;
    int base = u0 * V + v0;
    Bl b;
    b.i00 = base;     b.i10 = base + V;
    b.i01 = base + 1; b.i11 = base + V + 1;
    b.w00 = (1.0f - fu) * (1.0f - fv);
    b.w10 = fu * (1.0f - fv);
    b.w01 = (1.0f - fu) * fv;
    b.w11 = fu * fv;
    return b;
}

static __device__ __forceinline__ float4 ld_h4(const uint2* __restrict__ s, int idx) {
    uint2 r = s[idx];
    __half2 h01 = *reinterpret_cast<__half2*>(&r.x);
    __half2 h23 = *reinterpret_cast<__half2*>(&r.y);
    float2 f01 = __half22float2(h01);
    float2 f23 = __half22float2(h23);
    return make_float4(f01.x, f01.y, f23.x, f23.y);
}

template <int U, int V>
static __device__ __forceinline__ float4 bilin_h4(const uint2* __restrict__ s,
                                                  float cu, float cv) {
    Bl b = bl_setup<U, V>(cu, cv);
    float4 a = ld_h4(s, b.i00);
    float4 c = ld_h4(s, b.i10);
    float4 d = ld_h4(s, b.i01);
    float4 e = ld_h4(s, b.i11);
    float4 o;
    o.x = a.x * b.w00 + c.x * b.w10 + d.x * b.w01 + e.x * b.w11;
    o.y = a.y * b.w00 + c.y * b.w10 + d.y * b.w01 + e.y * b.w11;
    o.z = a.z * b.w00 + c.z * b.w10 + d.z * b.w01 + e.z * b.w11;
    o.w = a.w * b.w00 + c.w * b.w10 + d.w * b.w01 + e.w * b.w11;
    return o;
}

static __device__ __forceinline__ float2 gather_ra(const float2* __restrict__ t,
                                                   float rx, float ax) {
    int ui = (int)rintf(clip01(rx) * 2047.0f);
    int vi = (int)rintf(clip01(ax) * 2047.0f);
    return __ldg(t + (ui * 2048 + vi));
}

static __device__ __forceinline__ float2 ldcs2(const float2* p) {
    return __ldcs(p);
}

__global__ void __launch_bounds__(640, 2)
disneynet_kernel(const float2* __restrict__ roughNoh,
                 const float2* __restrict__ anisoToh,
                 const float2* __restrict__ nDotLV,
                 const float2* __restrict__ metalLoh,
                 const float2* __restrict__ subCg,
                 const float2* __restrict__ spst,
                 const float2* __restrict__ shst,
                 const float2* __restrict__ lumCs,
                 const float2* __restrict__ tabRAEnc,  // 2048x2048x2 (global/L2)
                 const float*  __restrict__ tabCgEnc,  // 2048
                 const float*  __restrict__ tabRSEnc,  // 64x64x3
                 const float*  __restrict__ tabRADec,  // 48x48x3
                 const float2* __restrict__ tabCgDec,  // 96x2
                 const float*  __restrict__ tabLVR,    // 32x32
                 const float4* __restrict__ tabLV,     // 32x32x4
                 const float4* __restrict__ tabNHL,    // 32x32x4
                 float2* __restrict__ out,
                 int n) {
    extern __shared__ float smem[];
    uint2*  sRS   = (uint2*)(smem + OFF_RS);
    uint2*  sLV   = (uint2*)(smem + OFF_LV);
    uint2*  sNHL  = (uint2*)(smem + OFF_NHL);
    float2* sRA01 = (float2*)(smem + OFF_RA01);
    float*  sRA2  = smem + OFF_RA2;
    __half* sLVR  = (__half*)(smem + OFF_LVR);
    float2* sCgF  = (float2*)(smem + OFF_CGF);

    const int tid = threadIdx.x;
    const int nthr = blockDim.x;

    // ---- stage tables ----
    for (int idx = tid; idx < 64 * 64; idx += nthr) {
        const float* src = tabRSEnc + idx * 3;
        __half2 h01 = __floats2half2_rn(triw(src[0]), triw(src[1]));
        __half2 h23 = __floats2half2_rn(triw(src[2]), 0.0f);
        uint2 r;
        r.x = *reinterpret_cast<unsigned*>(&h01);
        r.y = *reinterpret_cast<unsigned*>(&h23);
        sRS[idx] = r;
    }
    for (int idx = tid; idx < 32 * 32; idx += nthr) {
        float4 v = tabLV[idx];
        __half2 a = __floats2half2_rn(triw(v.x), triw(v.y));
        __half2 b = __floats2half2_rn(triw(v.z), triw(v.w));
        uint2 r;
        r.x = *reinterpret_cast<unsigned*>(&a);
        r.y = *reinterpret_cast<unsigned*>(&b);
        sLV[idx] = r;
        float4 w = tabNHL[idx];
        __half2 c = __floats2half2_rn(triw(w.x), triw(w.y));
        __half2 d = __floats2half2_rn(triw(w.z), triw(w.w));
        uint2 q;
        q.x = *reinterpret_cast<unsigned*>(&c);
        q.y = *reinterpret_cast<unsigned*>(&d);
        sNHL[idx] = q;
        sLVR[idx] = __float2half_rn(triw(tabLVR[idx]));
    }
    for (int idx = tid; idx < 48 * 48; idx += nthr) {
        const float* src = tabRADec + idx * 3;
        sRA01[idx] = make_float2(src[0], src[1]);
        sRA2[idx]  = src[2];
    }
    // Fused cg chain: ci -> triw(tabCgEnc[ci]) -> bilinear(tabCgDec).
    for (int idx = tid; idx < 2048; idx += nthr) {
        float cg0 = triw(tabCgEnc[idx]);
        float u = clip01(cg0) * 95.0f;
        float u0f = floorf(u);
        float fu = u - u0f;
        int u0 = (int)u0f;
        int u1 = min(u0 + 1, 95);
        float2 a = tabCgDec[u0];
        float2 b = tabCgDec[u1];
        sCgF[idx] = make_float2(a.x * (1.0f - fu) + b.x * fu,
                                a.y * (1.0f - fu) + b.y * fu);
    }
    __syncthreads();

    const int stride = gridDim.x * nthr;
    const int i0 = blockIdx.x * nthr + tid;

    // Prologue: first iteration's gather.
    float2 rn, at, raRaw;
    if (i0 < n) {
        rn = ldcs2(roughNoh + i0);
        at = ldcs2(anisoToh + i0);
        raRaw = gather_ra(tabRAEnc, rn.x, at.x);
    }

    for (int i = i0; i < n; i += stride) {
        // Prefetch next iteration's gather (hides L2 latency behind this body).
        const int j = i + stride;
        float2 rn_n, at_n, raRaw_n;
        if (j < n) {
            rn_n = ldcs2(roughNoh + j);
            at_n = ldcs2(anisoToh + j);
            raRaw_n = gather_ra(tabRAEnc, rn_n.x, at_n.x);
        }

        const float2 nl = ldcs2(nDotLV + i);
        const float2 ml = ldcs2(metalLoh + i);
        const float2 sc = ldcs2(subCg + i);
        const float2 sp = ldcs2(spst + i);
        const float2 sh = ldcs2(shst + i);
        const float2 lc = ldcs2(lumCs + i);

        const float ra0 = triw(raRaw.x);
        const float ra1 = triw(raRaw.y);

        // fused cg -> (cgC0, cgC1)
        int ci = (int)rintf(clip01(sc.y) * 2047.0f);
        float2 cgC = sCgF[ci];

        // rsEnc = bilinear (pre-normalized, fp16 values)
        float4 rs = bilin_h4<64, 64>(sRS, rn.x, sc.x);

        const float m = ml.x;
        const float om = 1.0f - m;
        const float cd  = om * lc.x;
        const float cm0 = sp.x * 0.1f * om * sp.y + m * lc.x;
        const float cm1 = sp.x * 0.1f * om * (1.0f - sp.y);
        const float cs0 = sh.x * om * sh.y;
        const float cs1 = sh.x * om * (1.0f - sh.y);
        const float ccv = 0.0625f * lc.y;

        const float rsCd0 = rs.x * cd;
        const float rsCd1 = rs.y * cd;
        const float rsCd2 = rs.z * cd;

        // raCoefs = bilinear, fp32 SoA (feeds den^2)
        float raC0, raC1, raC2;
        {
            Bl b = bl_setup<48, 48>(ra0, ra1);
            float2 a = sRA01[b.i00];
            float2 c = sRA01[b.i10];
            float2 d = sRA01[b.i01];
            float2 e = sRA01[b.i11];
            raC0 = a.x * b.w00 + c.x * b.w10 + d.x * b.w01 + e.x * b.w11;
            raC1 = a.y * b.w00 + c.y * b.w10 + d.y * b.w01 + e.y * b.w11;
            raC2 = sRA2[b.i00] * b.w00 + sRA2[b.i10] * b.w10
                 + sRA2[b.i01] * b.w01 + sRA2[b.i11] * b.w11;
        }

        // vTerm = bilinear, fp16 scalar table
        float vT;
        {
            Bl b = bl_setup<32, 32>(nl.x * nl.y, ra0);
            float a = __half2float(sLVR[b.i00]);
            float c = __half2float(sLVR[b.i10]);
            float d = __half2float(sLVR[b.i01]);
            float e = __half2float(sLVR[b.i11]);
            vT = a * b.w00 + c * b.w10 + d * b.w01 + e * b.w11;
        }

        // nlvCoefs / nhlCoefs (fp16 values)
        float4 nlv = bilin_h4<32, 32>(sLV, nl.x, nl.y);
        float4 nhl = bilin_h4<32, 32>(sNHL, ml.y, nl.x);

        const float noh2 = rn.y * rn.y;
        const float den = raC0 * at.y * at.y + raC1 * noh2 + raC2;
        const float dT = __fdividef(0.25f, nl.y * den * den);

        float x = rsCd0 * ml.y * nlv.y
                + rsCd1 * nlv.z
                + rsCd2 * nlv.w
                + cm0 * vT * nhl.z * dT
                + cs0 * nhl.x;

        float y = ((1.0f - cm1) * nhl.w + cm1) * vT * dT
                + cs1 * nhl.x
                + ccv * nhl.y * nlv.x * __fdividef(1.0f, nl.y * (cgC.x * noh2 + cgC.y));

        __stcs(out + i, make_float2(x, y));

        // rotate pipeline
        rn = rn_n;
        at = at_n;
        raRaw = raRaw_n;
    }
}

extern "C" void kernel_launch(void* const* d_in, const int* in_sizes, int n_in,
                              void* d_out, int out_size) {
    // Input order:
    // 0 roughNoh 1 anisoToh 2 nDotLV 3 tDotLV(unused) 4 metalLoh 5 subCg
    // 6 spst 7 shst 8 lumCs 9 tabRAEnc 10 tabCgEnc 11 tabRSEnc 12 tabRADec
    // 13 tabCgDec 14 tabLVR 15 tabLV 16 tabNHL
    const int n = in_sizes[0] / 2;

    static bool attr_set = false;
    if (!attr_set) {
        cudaFuncSetAttribute(disneynet_kernel,
                             cudaFuncAttributeMaxDynamicSharedMemorySize,
                             SMEM_BYTES);
        attr_set = true;
    }

    const int threads = 640;
    const int blocks = 296;  // 2 CTAs/SM x 148 SMs, persistent
    disneynet_kernel<<<blocks, threads, SMEM_BYTES>>>(
        (const float2*)d_in[0],
        (const float2*)d_in[1],
        (const float2*)d_in[2],
        (const float2*)d_in[4],
        (const float2*)d_in[5],
        (const float2*)d_in[6],
        (const float2*)d_in[7],
        (const float2*)d_in[8],
        (const float2*)d_in[9],
        (const float*)d_in[10],
        (const float*)d_in[11],
        (const float*)d_in[12],
        (const float2*)d_in[13],
        (const float*)d_in[14],
        (const float4*)d_in[15],
        (const float4*)d_in[16],
        (float2*)d_out,
        n);
}